// round 11
// baseline (speedup 1.0000x reference)
#include <cuda_runtime.h>
#include <cuda_fp16.h>

#define SB   32      // S*B
#define NTOK 2048    // N
#define KK   16      // K
#define DD   32      // D
#define HH   128     // H

#define TPB   256    // threads per block (8 warps)
#define TOKPB 64     // tokens per block
#define NW    8      // warps (warp = 16-h slice)
#define TT    2      // token-groups per thread

typedef unsigned long long u64;

// hk[k,h]+b1[h] per (s,b), packed half2. 32*16*64 u32 = 128 KB.
__device__ unsigned g_hkbh[SB * KK * (HH / 2)];

__device__ __forceinline__ u64 pk2(float lo, float hi) {
    u64 r; asm("mov.b64 %0, {%1, %2};" : "=l"(r) : "f"(lo), "f"(hi)); return r;
}
__device__ __forceinline__ void upk2(float& lo, float& hi, u64 v) {
    asm("mov.b64 {%0, %1}, %2;" : "=f"(lo), "=f"(hi) : "l"(v));
}
__device__ __forceinline__ u64 fma2(u64 a, u64 b, u64 c) {
    u64 r; asm("fma.rn.f32x2 %0, %1, %2, %3;" : "=l"(r) : "l"(a), "l"(b), "l"(c)); return r;
}
__device__ __forceinline__ __half2 tanh2(__half2 v) {
    unsigned vi = *reinterpret_cast<unsigned*>(&v), yi;
    asm("tanh.approx.f16x2 %0, %1;" : "=r"(yi) : "r"(vi));
    return *reinterpret_cast<__half2*>(&yi);
}
__device__ __forceinline__ __half2 asH2(unsigned u) { return *reinterpret_cast<__half2*>(&u); }
__device__ __forceinline__ unsigned h2bits(__half2 h) { return *reinterpret_cast<unsigned*>(&h); }

// ---------------------------------------------------------------------------
// Prep: hkbh[sb,k,h/2] = half2( sum_d mu*Wm + tau*Wt + b1 )
// ---------------------------------------------------------------------------
__global__ void prep_kernel(const float* __restrict__ mu,
                            const float* __restrict__ tau,
                            const float* __restrict__ W1,
                            const float* __restrict__ b1) {
    int k  = blockIdx.x;
    int sb = blockIdx.y;
    int t  = threadIdx.x;               // 0..63 -> h pair (2t, 2t+1)
    const float* mur  = mu  + (sb * KK + k) * DD;
    const float* taur = tau + (sb * KK + k) * DD;
    int h0 = 2 * t, h1 = 2 * t + 1;
    float s0 = b1[h0], s1 = b1[h1];
    #pragma unroll
    for (int d = 0; d < DD; d++) {
        float m = mur[d], ta = taur[d];
        s0 = fmaf(m,  W1[(DD     + d) * HH + h0], s0);
        s1 = fmaf(m,  W1[(DD     + d) * HH + h1], s1);
        s0 = fmaf(ta, W1[(2 * DD + d) * HH + h0], s0);
        s1 = fmaf(ta, W1[(2 * DD + d) * HH + h1], s1);
    }
    g_hkbh[(sb * KK + k) * (HH / 2) + t] = h2bits(__floats2half2_rn(s0, s1));
}

// ---------------------------------------------------------------------------
// Main: block = 8 warps x 64 tokens. Warp w owns h-slice [16w,16w+16);
// thread register-blocks TT=2 token groups. Phase A runs in TWO h-halves of 8
// so only 8 u64 accumulators are live at once (reg cap 64 -> 4 blocks/SM).
// Phase B: all-f16 inner loop, results straight to padded smem; one sync.
// ---------------------------------------------------------------------------
__global__ __launch_bounds__(TPB, 4)
void main_kernel(const float* __restrict__ x,
                 const float* __restrict__ W1,
                 const float* __restrict__ W2,
                 float* __restrict__ out) {
    __shared__ unsigned hkb_s[KK * (HH / 2)];        //  4 KB
    __shared__ float    xT_s[DD][TOKPB + 1];         //  8.1 KB (padded rows)
    __shared__ float    part_s[NW][TOKPB][KK + 1];   // 34.8 KB (stride-17 rows)

    const int tid  = threadIdx.x;
    const int w    = tid >> 5;                       // warp id = h-slice
    const int lane = tid & 31;
    const int sb   = blockIdx.y;
    const int tokb = blockIdx.x * TOKPB;
    const int h0   = w * 16;

    for (int i = tid; i < KK * (HH / 2); i += TPB)
        hkb_s[i] = g_hkbh[sb * KK * (HH / 2) + i];

    // Stage x transposed: xT_s[d][tok] (coalesced LDG.128, one step)
    #pragma unroll
    for (int it = 0; it < 2; it++) {
        int idx = tid + it * TPB;                    // 0..511 = 64 tok x 8 quads
        int tok = idx >> 3, q = idx & 7;
        float4 v = *reinterpret_cast<const float4*>(
            x + ((size_t)sb * NTOK + tokb + tok) * DD + q * 4);
        xT_s[q * 4 + 0][tok] = v.x; xT_s[q * 4 + 1][tok] = v.y;
        xT_s[q * 4 + 2][tok] = v.z; xT_s[q * 4 + 3][tok] = v.w;
    }
    __syncthreads();

    // ---- Phase A: hx (f32, FFMA2) in two h-halves of 8 ----
    unsigned hxh[TT][8];
    #pragma unroll 1
    for (int hf = 0; hf < 2; hf++) {
        u64 hx2[TT][4];
        #pragma unroll
        for (int t = 0; t < TT; t++)
            #pragma unroll
            for (int j = 0; j < 4; j++) hx2[t][j] = 0ull;

        #pragma unroll
        for (int d = 0; d < DD; d++) {
            const ulonglong2* wrow =
                reinterpret_cast<const ulonglong2*>(W1 + d * HH + h0 + hf * 8);
            ulonglong2 wa = __ldg(wrow + 0);         // warp-uniform LDG.128
            ulonglong2 wb = __ldg(wrow + 1);
            #pragma unroll
            for (int t = 0; t < TT; t++) {
                float xv = xT_s[d][t * 32 + lane];   // conflict-free LDS.32
                u64 x2 = pk2(xv, xv);
                hx2[t][0] = fma2(x2, wa.x, hx2[t][0]);
                hx2[t][1] = fma2(x2, wa.y, hx2[t][1]);
                hx2[t][2] = fma2(x2, wb.x, hx2[t][2]);
                hx2[t][3] = fma2(x2, wb.y, hx2[t][3]);
            }
        }
        // convert this half to half2 immediately (frees hx2 regs)
        #pragma unroll
        for (int t = 0; t < TT; t++)
            #pragma unroll
            for (int q = 0; q < 4; q++) {
                float lo, hi;
                upk2(lo, hi, hx2[t][q]);
                hxh[t][hf * 4 + q] = h2bits(__floats2half2_rn(lo, hi));
            }
    }

    // W2 slice as half2 (warp-uniform LDG)
    __half2 w2h[8];
    {
        const float4* w2p = reinterpret_cast<const float4*>(W2 + h0);
        #pragma unroll
        for (int q = 0; q < 4; q++) {
            float4 wv = __ldg(w2p + q);
            w2h[2 * q + 0] = __floats2half2_rn(wv.x, wv.y);
            w2h[2 * q + 1] = __floats2half2_rn(wv.z, wv.w);
        }
    }

    // ---- Phase B: all-f16 inner loop, results straight to smem ----
    #pragma unroll
    for (int k = 0; k < KK; k++) {
        const uint4* hkp = reinterpret_cast<const uint4*>(&hkb_s[k * (HH / 2) + w * 8]);
        uint4 hA = hkp[0], hB = hkp[1];              // warp-uniform LDS.128
        #pragma unroll
        for (int t = 0; t < TT; t++) {
            __half2 a0, a1, a2, a3;
            a0 = __hmul2(tanh2(__hadd2(asH2(hxh[t][0]), asH2(hA.x))), w2h[0]);
            a1 = __hmul2(tanh2(__hadd2(asH2(hxh[t][1]), asH2(hA.y))), w2h[1]);
            a2 = __hmul2(tanh2(__hadd2(asH2(hxh[t][2]), asH2(hA.z))), w2h[2]);
            a3 = __hmul2(tanh2(__hadd2(asH2(hxh[t][3]), asH2(hA.w))), w2h[3]);
            a0 = __hfma2(tanh2(__hadd2(asH2(hxh[t][4]), asH2(hB.x))), w2h[4], a0);
            a1 = __hfma2(tanh2(__hadd2(asH2(hxh[t][5]), asH2(hB.y))), w2h[5], a1);
            a2 = __hfma2(tanh2(__hadd2(asH2(hxh[t][6]), asH2(hB.z))), w2h[6], a2);
            a3 = __hfma2(tanh2(__hadd2(asH2(hxh[t][7]), asH2(hB.w))), w2h[7], a3);
            float2 f01 = __half22float2(__hadd2(a0, a1));
            float2 f23 = __half22float2(__hadd2(a2, a3));
            // stride-17 rows: bank = lane*17 mod 64, conflict-free STS.32
            part_s[w][t * 32 + lane][k] = (f01.x + f01.y) + (f23.x + f23.y);
        }
    }
    __syncthreads();

    // ---- Reduce + softmax: thread = (token = tid>>2, k-quad = tid&3) ----
    const int tok = tid >> 2;
    const int kq  = tid & 3;
    float g[4];
    #pragma unroll
    for (int j = 0; j < 4; j++) {
        int k = 4 * kq + j;
        float s = 0.f;
        #pragma unroll
        for (int ww = 0; ww < NW; ww++) s += part_s[ww][tok][k];
        g[j] = s;
    }

    float m = fmaxf(fmaxf(g[0], g[1]), fmaxf(g[2], g[3]));
    m = fmaxf(m, __shfl_xor_sync(0xffffffffu, m, 1));
    m = fmaxf(m, __shfl_xor_sync(0xffffffffu, m, 2));

    float e0 = __expf(g[0] - m), e1 = __expf(g[1] - m);
    float e2 = __expf(g[2] - m), e3 = __expf(g[3] - m);
    float s = (e0 + e1) + (e2 + e3);
    s += __shfl_xor_sync(0xffffffffu, s, 1);
    s += __shfl_xor_sync(0xffffffffu, s, 2);
    float inv = __fdividef(1.f, s);

    float4 o;
    o.x = e0 * inv; o.y = e1 * inv; o.z = e2 * inv; o.w = e3 * inv;
    reinterpret_cast<float4*>(out + ((size_t)sb * NTOK + tokb + tok) * KK)[kq] = o;
}

extern "C" void kernel_launch(void* const* d_in, const int* in_sizes, int n_in,
                              void* d_out, int out_size) {
    const float* x   = (const float*)d_in[0];
    const float* mu  = (const float*)d_in[1];
    const float* tau = (const float*)d_in[2];
    const float* W1  = (const float*)d_in[3];
    const float* b1  = (const float*)d_in[4];
    const float* W2  = (const float*)d_in[5];
    // d_in[6] = b2: cancels in softmax, unused.
    float* out = (float*)d_out;

    prep_kernel<<<dim3(KK, SB), HH / 2>>>(mu, tau, W1, b1);
    main_kernel<<<dim3(NTOK / TOKPB, SB), TPB>>>(x, W1, W2, out);
}